// round 2
// baseline (speedup 1.0000x reference)
#include <cuda_runtime.h>
#include <cstdint>

// Problem shape (fixed by setup_inputs)
#define NPTS   8192      // num_points (refs and queries)
#define NFEAT  256       // num_feat
#define SPLITS 8         // reference-dim splits
#define CHUNK  (NPTS / SPLITS)   // 1024 refs per block -> 16KB smem as float4

// Per-split packed argmin partials: (ordered_d2_bits << 32) | ref_index.
// Every slot is written by a plain store each call -> no init, no atomics.
__device__ unsigned long long g_part[SPLITS * NPTS];

// Map float to a monotonically ordered uint (total order == float order).
__device__ __forceinline__ unsigned int float_order(float f) {
    unsigned int u = __float_as_uint(f);
    return (u & 0x80000000u) ? ~u : (u | 0x80000000u);
}

// grid(NPTS/256, SPLITS), block(256). One query per thread, CHUNK refs in smem
// as float4{x,y,z,|r|^2}. argmin_i (|r_i|^2 - 2 q.r_i) == argmin_i d2(i, q).
__global__ void __launch_bounds__(256) nn_argmin_kernel(
    const float* __restrict__ t1,   // refs  [3, NPTS]
    const float* __restrict__ t2)   // query [3, NPTS]
{
    __shared__ float4 refs[CHUNK];
    const int base = blockIdx.y * CHUNK;
    const int tid  = threadIdx.x;

    // Vectorized cooperative load: each thread loads one float4 per row.
    {
        const int r4 = tid * 4;  // CHUNK/256 == 4
        float4 x4 = *(const float4*)(t1 + base + r4);
        float4 y4 = *(const float4*)(t1 + NPTS + base + r4);
        float4 z4 = *(const float4*)(t1 + 2 * NPTS + base + r4);
        refs[r4 + 0] = make_float4(x4.x, y4.x, z4.x, fmaf(x4.x, x4.x, fmaf(y4.x, y4.x, z4.x * z4.x)));
        refs[r4 + 1] = make_float4(x4.y, y4.y, z4.y, fmaf(x4.y, x4.y, fmaf(y4.y, y4.y, z4.y * z4.y)));
        refs[r4 + 2] = make_float4(x4.z, y4.z, z4.z, fmaf(x4.z, x4.z, fmaf(y4.z, y4.z, z4.z * z4.z)));
        refs[r4 + 3] = make_float4(x4.w, y4.w, z4.w, fmaf(x4.w, x4.w, fmaf(y4.w, y4.w, z4.w * z4.w)));
    }
    __syncthreads();

    const int q = blockIdx.x * 256 + tid;
    const float a = -2.0f * t2[q];
    const float b = -2.0f * t2[NPTS + q];
    const float c = -2.0f * t2[2 * NPTS + q];

    // 4 rotating partial minima break the loop-carried min dependency.
    float best[4] = {3.4e38f, 3.4e38f, 3.4e38f, 3.4e38f};
    int   bidx[4] = {0, 0, 0, 0};

    #pragma unroll 2
    for (int r = 0; r < CHUNK; r += 8) {
        #pragma unroll
        for (int u = 0; u < 8; ++u) {
            float4 f = refs[r + u];
            float v = fmaf(a, f.x, fmaf(b, f.y, fmaf(c, f.z, f.w)));
            int p = u & 3;
            if (v < best[p]) { best[p] = v; bidx[p] = r + u; }
        }
    }

    // Combine partials -> packed key; ties resolve to the lowest index
    // (matches jnp.argmin first-occurrence semantics).
    unsigned long long key = 0xFFFFFFFFFFFFFFFFull;
    #pragma unroll
    for (int u = 0; u < 4; ++u) {
        unsigned long long k =
            ((unsigned long long)float_order(best[u]) << 32) |
            (unsigned int)(base + bidx[u]);
        key = (k < key) ? k : key;
    }
    g_part[blockIdx.y * NPTS + q] = key;
}

// grid(NPTS/1024, 512/GROWS), block(256). Each thread owns 4 consecutive
// queries (float4 stores). Rows [0,256): gather emb1[f][ind[j]] (L2-resident);
// rows [256,512): straight float4 copy of emb2.
#define GROWS 32
__global__ void __launch_bounds__(256) gather_concat_kernel(
    const float* __restrict__ emb1,
    const float* __restrict__ emb2,
    float* __restrict__ out)
{
    const int tid   = threadIdx.x;
    const int jbase = blockIdx.x * 1024 + tid * 4;
    const int f0    = blockIdx.y * GROWS;

    if (f0 < NFEAT) {
        // Combine the 8 split partials for this thread's 4 queries.
        int ind[4];
        #pragma unroll
        for (int k = 0; k < 4; ++k) {
            unsigned long long m = 0xFFFFFFFFFFFFFFFFull;
            #pragma unroll
            for (int s = 0; s < SPLITS; ++s) {
                unsigned long long v = g_part[s * NPTS + jbase + k];
                m = (v < m) ? v : m;
            }
            ind[k] = (int)(unsigned int)(m & 0xFFFFFFFFull);
        }
        #pragma unroll 8
        for (int r = 0; r < GROWS; ++r) {
            const float* row = emb1 + (size_t)(f0 + r) * NPTS;
            float4 v = make_float4(row[ind[0]], row[ind[1]], row[ind[2]], row[ind[3]]);
            *(float4*)(out + (size_t)(f0 + r) * NPTS + jbase) = v;
        }
    } else {
        #pragma unroll 8
        for (int r = 0; r < GROWS; ++r) {
            const int f = f0 + r;
            float4 v = *(const float4*)(emb2 + (size_t)(f - NFEAT) * NPTS + jbase);
            *(float4*)(out + (size_t)f * NPTS + jbase) = v;
        }
    }
}

extern "C" void kernel_launch(void* const* d_in, const int* in_sizes, int n_in,
                              void* d_out, int out_size) {
    const float* emb1 = (const float*)d_in[0];
    const float* emb2 = (const float*)d_in[1];
    const float* t1   = (const float*)d_in[2];
    const float* t2   = (const float*)d_in[3];
    float* out = (float*)d_out;

    dim3 nn_grid(NPTS / 256, SPLITS);
    nn_argmin_kernel<<<nn_grid, 256>>>(t1, t2);

    dim3 g_grid(NPTS / 1024, (2 * NFEAT) / GROWS);
    gather_concat_kernel<<<g_grid, 256>>>(emb1, emb2, out);
}